// round 2
// baseline (speedup 1.0000x reference)
#include <cuda_runtime.h>
#include <cstdint>
#include <cstddef>

// ---------------------------------------------------------------------------
// LSTM_87351044866551
//   x[256,128,2048] fp32, Wi[2048,512], Uh[128,512], b[512], Wout[128,2], bout[2]
//   out[256,2] fp32
//
// Kernel 1: xg = x @ Wi   (M=32768, K=2048, N=512) fp32 SGEMM -> g_xg scratch
// Kernel 2: per-CTA LSTM recurrence (2 batch elems / CTA, Uh resident in
//           SMEM(104 rows)+regs(24 rows)), fused output head.
// ---------------------------------------------------------------------------

#define M_DIM 32768
#define N_DIM 512
#define K_DIM 2048

// 64 MB scratch for xg (allocation-free rule: __device__ global array)
__device__ float g_xg[(size_t)M_DIM * N_DIM];

// ===========================================================================
// Kernel 1: classic 128x128x8 double-buffered SGEMM, 8x8 register tile
// ===========================================================================
__global__ __launch_bounds__(256) void sgemm_xWi(const float* __restrict__ A,
                                                 const float* __restrict__ B) {
    __shared__ float As[2][8][128];
    __shared__ float Bs[2][8][128];

    const int tid  = threadIdx.x;
    const int row0 = blockIdx.y * 128;
    const int col0 = blockIdx.x * 128;

    // A tile load: 128 rows x 8 k; one float4 along k per thread
    const int a_row = tid >> 1;         // 0..127
    const int a_k   = (tid & 1) << 2;   // 0 or 4
    // B tile load: 8 k-rows x 128 n; one float4 along n per thread
    const int b_k = tid >> 5;           // 0..7
    const int b_n = (tid & 31) << 2;    // 0..124

    const float* Aptr = A + (size_t)(row0 + a_row) * K_DIM + a_k;
    const float* Bptr = B + (size_t)b_k * N_DIM + col0 + b_n;

    const int tx = tid & 15;
    const int ty = tid >> 4;

    float acc[8][8];
#pragma unroll
    for (int i = 0; i < 8; i++)
#pragma unroll
        for (int j = 0; j < 8; j++) acc[i][j] = 0.f;

    float4 a4 = *(const float4*)Aptr;
    float4 b4 = *(const float4*)Bptr;
    As[0][a_k + 0][a_row] = a4.x;
    As[0][a_k + 1][a_row] = a4.y;
    As[0][a_k + 2][a_row] = a4.z;
    As[0][a_k + 3][a_row] = a4.w;
    *(float4*)&Bs[0][b_k][b_n] = b4;
    __syncthreads();

    const int NT = K_DIM / 8;  // 256
    int buf = 0;
    for (int kt = 0; kt < NT; kt++) {
        if (kt + 1 < NT) {
            a4 = *(const float4*)(Aptr + (kt + 1) * 8);
            b4 = *(const float4*)(Bptr + (size_t)(kt + 1) * 8 * N_DIM);
        }
#pragma unroll
        for (int kk = 0; kk < 8; kk++) {
            float ar[8], br[8];
            *(float4*)&ar[0] = *(const float4*)&As[buf][kk][ty * 4];
            *(float4*)&ar[4] = *(const float4*)&As[buf][kk][64 + ty * 4];
            *(float4*)&br[0] = *(const float4*)&Bs[buf][kk][tx * 4];
            *(float4*)&br[4] = *(const float4*)&Bs[buf][kk][64 + tx * 4];
#pragma unroll
            for (int i = 0; i < 8; i++)
#pragma unroll
                for (int j = 0; j < 8; j++) acc[i][j] += ar[i] * br[j];
        }
        if (kt + 1 < NT) {
            buf ^= 1;
            As[buf][a_k + 0][a_row] = a4.x;
            As[buf][a_k + 1][a_row] = a4.y;
            As[buf][a_k + 2][a_row] = a4.z;
            As[buf][a_k + 3][a_row] = a4.w;
            *(float4*)&Bs[buf][b_k][b_n] = b4;
        }
        __syncthreads();
    }

#pragma unroll
    for (int i = 0; i < 8; i++) {
        const int r = row0 + ((i < 4) ? (ty * 4 + i) : (64 + ty * 4 + (i - 4)));
        float* Cp = g_xg + (size_t)r * N_DIM + col0;
        *(float4*)&Cp[tx * 4]      = make_float4(acc[i][0], acc[i][1], acc[i][2], acc[i][3]);
        *(float4*)&Cp[64 + tx * 4] = make_float4(acc[i][4], acc[i][5], acc[i][6], acc[i][7]);
    }
}

// ===========================================================================
// Kernel 2: LSTM recurrence, 2 batch elements per CTA, 512 threads
// ===========================================================================
__device__ __forceinline__ float fsig(float x) {
    return 1.f / (1.f + __expf(-x));
}
__device__ __forceinline__ float ftanh(float x) {
    // tanh(x) = 1 - 2/(exp(2x)+1); robust at both tails
    return 1.f - 2.f / (__expf(2.f * x) + 1.f);
}

// SMEM layout (floats): Us[512*108] (104 k-rows per gate column, stride 108),
//                       hs[2*128], zs[2*512]
#define US_FLOATS (512 * 108)
#define SM2_FLOATS (US_FLOATS + 256 + 1024)

__global__ __launch_bounds__(512) void lstm_rec(const float* __restrict__ Uh,
                                                const float* __restrict__ bias,
                                                const float* __restrict__ Wout,
                                                const float* __restrict__ bout,
                                                float* __restrict__ out) {
    extern __shared__ float sm[];
    float* Us = sm;                // per-column Uh, k = 0..103
    float* hs = sm + US_FLOATS;    // h state: [2][128]
    float* zs = hs + 256;          // activated gates: [2][512]

    const int tid = threadIdx.x;   // == gate column g, 0..511
    const int g   = tid;
    const int b0  = blockIdx.x * 2;

    // Load Uh column g: rows 0..103 -> SMEM (coalesced across g), 104..127 -> regs
    for (int k = 0; k < 104; k++) Us[g * 108 + k] = Uh[k * 512 + g];
    float wreg[24];
#pragma unroll
    for (int r = 0; r < 24; r++) wreg[r] = Uh[(104 + r) * 512 + g];
    const float bg   = bias[g];
    const int  gate  = g >> 7;     // 0:i 1:f 2:g 3:o

    if (tid < 256) hs[tid] = 0.f;
    float c = 0.f;                 // cell state carry (threads 0..255)
    __syncthreads();

    const float* xp0 = g_xg + ((size_t)b0 * 128) * 512 + g;
    const float* xp1 = g_xg + ((size_t)(b0 + 1) * 128) * 512 + g;
    float x0 = xp0[0];
    float x1 = xp1[0];

    for (int t = 0; t < 128; t++) {
        float z0 = x0 + bg;
        float z1 = x1 + bg;
        if (t + 1 < 128) {   // prefetch next timestep's xg contribution
            x0 = xp0[(t + 1) * 512];
            x1 = xp1[(t + 1) * 512];
        }

        // z += h @ Uh  (SMEM part: conflict-free float4 column reads)
        const float4* uv = (const float4*)(Us + g * 108);
        const float4* h0 = (const float4*)hs;
        const float4* h1 = (const float4*)(hs + 128);
#pragma unroll
        for (int q = 0; q < 26; q++) {
            float4 u = uv[q];
            float4 ha = h0[q];
            float4 hb = h1[q];
            z0 += u.x * ha.x; z0 += u.y * ha.y; z0 += u.z * ha.z; z0 += u.w * ha.w;
            z1 += u.x * hb.x; z1 += u.y * hb.y; z1 += u.z * hb.z; z1 += u.w * hb.w;
        }
        // register part: rows 104..127 (hs reads are broadcasts)
#pragma unroll
        for (int r = 0; r < 24; r++) {
            z0 += wreg[r] * hs[104 + r];
            z1 += wreg[r] * hs[128 + 104 + r];
        }

        // per-column activation
        float a0, a1;
        if (gate == 2) { a0 = ftanh(z0); a1 = ftanh(z1); }
        else           { a0 = fsig(z0);  a1 = fsig(z1);  }
        zs[g]       = a0;
        zs[512 + g] = a1;
        __syncthreads();

        // combine gates -> c, h (threads 0..255: one (batch, j) pair each)
        if (tid < 256) {
            const int bl = tid >> 7;
            const int jj = tid & 127;
            const float* zb = zs + bl * 512;
            const float ig = zb[jj];
            const float fg = zb[128 + jj];
            const float gg = zb[256 + jj];  // already tanh'd
            const float og = zb[384 + jj];
            c = fg * c + ig * gg;
            hs[bl * 128 + jj] = og * ftanh(c);
        }
        __syncthreads();
    }

    // Output head: out[b] = h_f @ Wout + bout   (O = 2)
    if (tid < 256) {
        const int bl = tid >> 7;
        const int jj = tid & 127;
        const float h = hs[bl * 128 + jj];
        float p0 = h * Wout[jj * 2 + 0];
        float p1 = h * Wout[jj * 2 + 1];
#pragma unroll
        for (int off = 16; off > 0; off >>= 1) {
            p0 += __shfl_down_sync(0xffffffffu, p0, off);
            p1 += __shfl_down_sync(0xffffffffu, p1, off);
        }
        if ((tid & 31) == 0) {     // warps 0..3 -> bl 0, warps 4..7 -> bl 1
            const int w = tid >> 5;
            zs[w * 2 + 0] = p0;
            zs[w * 2 + 1] = p1;
        }
    }
    __syncthreads();
    if (tid < 2) {
        float s0 = bout[0], s1 = bout[1];
#pragma unroll
        for (int w = 0; w < 4; w++) {
            s0 += zs[(tid * 4 + w) * 2 + 0];
            s1 += zs[(tid * 4 + w) * 2 + 1];
        }
        out[(b0 + tid) * 2 + 0] = s0;
        out[(b0 + tid) * 2 + 1] = s1;
    }
}

// ===========================================================================
extern "C" void kernel_launch(void* const* d_in, const int* in_sizes, int n_in,
                              void* d_out, int out_size) {
    const float* x    = (const float*)d_in[0];
    const float* Wi   = (const float*)d_in[1];
    const float* Uh   = (const float*)d_in[2];
    const float* b    = (const float*)d_in[3];
    const float* Wout = (const float*)d_in[4];
    const float* bout = (const float*)d_in[5];
    float* out = (float*)d_out;

    dim3 grid1(N_DIM / 128, M_DIM / 128);   // (4, 256)
    sgemm_xWi<<<grid1, 256>>>(x, Wi);

    const size_t smem2 = SM2_FLOATS * sizeof(float);  // 226,304 B
    cudaFuncSetAttribute(lstm_rec, cudaFuncAttributeMaxDynamicSharedMemorySize,
                         (int)smem2);
    lstm_rec<<<128, 512, smem2>>>(Uh, b, Wout, bout, out);
}

// round 4
// speedup vs baseline: 1.7467x; 1.7467x over previous
#include <cuda_runtime.h>
#include <cuda_bf16.h>
#include <cstdint>
#include <cstddef>

// ---------------------------------------------------------------------------
// LSTM_87351044866551  (Round 4: HMMA mma.sync bf16 3-term split GEMM)
//   tcgen05 is NOT assemblable on this harness (.target sm_103, no 'a'
//   feature) -> use base-ISA tensor path: ldmatrix + mma.sync + cp.async.
// Kernels:
//   P: transpose+split Wi -> g_wb_hi/lo bf16 [N=512][K=2048]
//   G: xg = x@Wi, CTA 128x256, warp 64x64, K-chunk 32, 3-term bf16 split
//   L: LSTM recurrence (unchanged)
// ---------------------------------------------------------------------------

#define M_DIM 32768
#define N_DIM 512
#define K_DIM 2048

__device__ float g_xg[(size_t)M_DIM * N_DIM];            // 64 MB scratch
__device__ __nv_bfloat16 g_wb_hi[(size_t)N_DIM * K_DIM]; // [n][k]
__device__ __nv_bfloat16 g_wb_lo[(size_t)N_DIM * K_DIM];

// ===========================================================================
// helpers (base ISA only)
// ===========================================================================
__device__ __forceinline__ uint32_t smem_u32(const void* p) {
    uint32_t a;
    asm("{ .reg .u64 t; cvta.to.shared.u64 t, %1; cvt.u32.u64 %0, t; }"
        : "=r"(a) : "l"(p));
    return a;
}
__device__ __forceinline__ void ldsm_x4(uint32_t& r0, uint32_t& r1,
                                        uint32_t& r2, uint32_t& r3,
                                        uint32_t addr) {
    asm volatile("ldmatrix.sync.aligned.m8n8.x4.shared.b16 {%0,%1,%2,%3},[%4];"
                 : "=r"(r0), "=r"(r1), "=r"(r2), "=r"(r3) : "r"(addr));
}
__device__ __forceinline__ void mma_bf16(float* d, const uint32_t* a,
                                         uint32_t b0, uint32_t b1) {
    asm volatile(
        "mma.sync.aligned.m16n8k16.row.col.f32.bf16.bf16.f32 "
        "{%0,%1,%2,%3},{%4,%5,%6,%7},{%8,%9},{%0,%1,%2,%3};"
        : "+f"(d[0]), "+f"(d[1]), "+f"(d[2]), "+f"(d[3])
        : "r"(a[0]), "r"(a[1]), "r"(a[2]), "r"(a[3]), "r"(b0), "r"(b1));
}
#define CPASYNC16(dst, src) \
    asm volatile("cp.async.cg.shared.global [%0],[%1],16;" :: "r"(dst), "l"(src))
#define CPCOMMIT() asm volatile("cp.async.commit_group;" ::: "memory")
#define CPWAIT0()  asm volatile("cp.async.wait_group 0;" ::: "memory")

// ===========================================================================
// Kernel P: Wb_hi/lo[n][k] = split(Wi[k][n])
// ===========================================================================
__global__ __launch_bounds__(1024) void prep_w(const float* __restrict__ Wi) {
    __shared__ float t[32][33];
    const int k = blockIdx.x * 32 + threadIdx.y;
    const int n = blockIdx.y * 32 + threadIdx.x;
    t[threadIdx.y][threadIdx.x] = Wi[(size_t)k * N_DIM + n];
    __syncthreads();
    const int n2 = blockIdx.y * 32 + threadIdx.y;
    const int k2 = blockIdx.x * 32 + threadIdx.x;
    const float v = t[threadIdx.x][threadIdx.y];
    const __nv_bfloat16 h = __float2bfloat16_rn(v);
    const __nv_bfloat16 l = __float2bfloat16_rn(v - __bfloat162float(h));
    g_wb_hi[(size_t)n2 * K_DIM + k2] = h;
    g_wb_lo[(size_t)n2 * K_DIM + k2] = l;
}

// ===========================================================================
// Kernel G: HMMA GEMM. SMEM stage layout (bf16 units, row stride 40 = 80B):
//   Ahi[128*40] @0, Alo @5120, Bhi[256*40] @10240, Blo @20480 -> 30720 units
// ===========================================================================
#define SROW 40
#define ST_ALO 5120
#define ST_BHI 10240
#define ST_BLO 20480
#define STAGE_U 30720              // bf16 units per stage
#define STAGE_B (STAGE_U * 2)      // 61440 bytes
#define GEMM_SMEM (2 * STAGE_B)    // 122880 bytes
#define NCHUNK 64                  // K / 32

__global__ __launch_bounds__(256, 1) void gemm_hmma(const float* __restrict__ x) {
    extern __shared__ __nv_bfloat16 smb[];
    const uint32_t sbase = smem_u32(smb);
    const int tid  = threadIdx.x;
    const int lane = tid & 31;
    const int w    = tid >> 5;
    const int wm   = w & 1;          // M warp coord (2)
    const int wn   = w >> 1;         // N warp coord (4)
    const int m0   = blockIdx.y * 128;
    const int n0   = blockIdx.x * 256;

    float acc[4][8][4];
#pragma unroll
    for (int a = 0; a < 4; a++)
#pragma unroll
        for (int b = 0; b < 8; b++)
#pragma unroll
            for (int c = 0; c < 4; c++) acc[a][b][c] = 0.f;

    // per-thread load indices
    // A: 1024 float4 per chunk -> 4/thread. idx -> r=idx>>3 (0..127), f4=idx&7
    // B: 1024 16B units per array -> 4/thread. idx -> n=idx>>2, ku=idx&3
    const float* xA = x + (size_t)m0 * K_DIM;
    const __nv_bfloat16* wh = g_wb_hi + (size_t)n0 * K_DIM;
    const __nv_bfloat16* wl = g_wb_lo + (size_t)n0 * K_DIM;

    float4 av[4];

#define LDG_A(kt)                                                               \
    do {                                                                        \
        _Pragma("unroll")                                                       \
        for (int i = 0; i < 4; i++) {                                           \
            const int idx = tid + i * 256;                                      \
            const int r = idx >> 3, f4 = idx & 7;                               \
            av[i] = *(const float4*)(xA + (size_t)r * K_DIM + (kt) * 32 + f4 * 4); \
        }                                                                       \
    } while (0)

#define STS_A(s)                                                                \
    do {                                                                        \
        _Pragma("unroll")                                                       \
        for (int i = 0; i < 4; i++) {                                           \
            const int idx = tid + i * 256;                                      \
            const int r = idx >> 3, f4 = idx & 7;                               \
            const float4 v = av[i];                                             \
            __nv_bfloat16 hx = __float2bfloat16_rn(v.x);                        \
            __nv_bfloat16 hy = __float2bfloat16_rn(v.y);                        \
            __nv_bfloat16 hz = __float2bfloat16_rn(v.z);                        \
            __nv_bfloat16 hw = __float2bfloat16_rn(v.w);                        \
            __nv_bfloat16 lx = __float2bfloat16_rn(v.x - __bfloat162float(hx)); \
            __nv_bfloat16 ly = __float2bfloat16_rn(v.y - __bfloat162float(hy)); \
            __nv_bfloat16 lz = __float2bfloat16_rn(v.z - __bfloat162float(hz)); \
            __nv_bfloat16 lw = __float2bfloat16_rn(v.w - __bfloat162float(hw)); \
            __nv_bfloat162 h01, h23, l01, l23;                                  \
            h01.x = hx; h01.y = hy; h23.x = hz; h23.y = hw;                     \
            l01.x = lx; l01.y = ly; l23.x = lz; l23.y = lw;                     \
            uint2 hp, lp;                                                       \
            hp.x = *(uint32_t*)&h01; hp.y = *(uint32_t*)&h23;                   \
            lp.x = *(uint32_t*)&l01; lp.y = *(uint32_t*)&l23;                   \
            const int u = r * SROW + f4 * 4;                                    \
            *(uint2*)(smb + (s) * STAGE_U + u)          = hp;                   \
            *(uint2*)(smb + (s) * STAGE_U + ST_ALO + u) = lp;                   \
        }                                                                       \
    } while (0)

#define CPA_B(kt, s)                                                            \
    do {                                                                        \
        _Pragma("unroll")                                                       \
        for (int i = 0; i < 4; i++) {                                           \
            const int idx = tid + i * 256;                                      \
            const int n = idx >> 2, ku = idx & 3;                               \
            const size_t gsrc = (size_t)n * K_DIM + (kt) * 32 + ku * 8;         \
            const uint32_t dst =                                                \
                sbase + (s) * STAGE_B + (ST_BHI + n * SROW + ku * 8) * 2;       \
            CPASYNC16(dst, wh + gsrc);                                          \
            CPASYNC16(dst + ST_BHI * 2, wl + gsrc);                             \
        }                                                                       \
    } while (0)

    // ---------------- prologue: chunk 0 into stage 0 ----------------
    LDG_A(0);
    CPA_B(0, 0);
    CPCOMMIT();
    STS_A(0);
    CPWAIT0();
    __syncthreads();

    // ldmatrix lane addressing (constant per thread)
    const int a_row = (lane & 7) + ((lane >> 3) & 1) * 8;  // + mi*16 + wm*64
    const int a_kb  = ((lane >> 4) & 1) * 16;              // + kk*32
    const int b_row = (lane & 7) + ((lane >> 4) & 1) * 8;  // + np*16 + wn*64
    const int b_kb  = ((lane >> 3) & 1) * 16;              // + kk*32

    for (int kt = 0; kt < NCHUNK; kt++) {
        const int s = kt & 1;
        if (kt + 1 < NCHUNK) {
            LDG_A(kt + 1);
            CPA_B(kt + 1, s ^ 1);
            CPCOMMIT();
        }

        const uint32_t stg = sbase + s * STAGE_B;
#pragma unroll
        for (int kk = 0; kk < 2; kk++) {
            uint32_t ah[4][4], al[4][4];
#pragma unroll
            for (int mi = 0; mi < 4; mi++) {
                const uint32_t aaddr =
                    stg + (wm * 64 + mi * 16 + a_row) * 80 + kk * 32 + a_kb;
                ldsm_x4(ah[mi][0], ah[mi][1], ah[mi][2], ah[mi][3], aaddr);
                ldsm_x4(al[mi][0], al[mi][1], al[mi][2], al[mi][3],
                        aaddr + ST_ALO * 2);
            }
#pragma unroll
            for (int np = 0; np < 4; np++) {
                const uint32_t baddr = stg + ST_BHI * 2 +
                    (wn * 64 + np * 16 + b_row) * 80 + kk * 32 + b_kb;
                uint32_t bh0, bh1, bh2, bh3, bl0, bl1, bl2, bl3;
                ldsm_x4(bh0, bh1, bh2, bh3, baddr);
                ldsm_x4(bl0, bl1, bl2, bl3, baddr + ST_BHI * 2);
#pragma unroll
                for (int mi = 0; mi < 4; mi++) {
                    mma_bf16(acc[mi][np * 2],     ah[mi], bh0, bh1);
                    mma_bf16(acc[mi][np * 2 + 1], ah[mi], bh2, bh3);
                }
#pragma unroll
                for (int mi = 0; mi < 4; mi++) {
                    mma_bf16(acc[mi][np * 2],     al[mi], bh0, bh1);
                    mma_bf16(acc[mi][np * 2 + 1], al[mi], bh2, bh3);
                }
#pragma unroll
                for (int mi = 0; mi < 4; mi++) {
                    mma_bf16(acc[mi][np * 2],     ah[mi], bl0, bl1);
                    mma_bf16(acc[mi][np * 2 + 1], ah[mi], bl2, bl3);
                }
            }
        }

        if (kt + 1 < NCHUNK) {
            STS_A(s ^ 1);
            CPWAIT0();
        }
        __syncthreads();
    }

    // ---------------- epilogue ----------------
#pragma unroll
    for (int mi = 0; mi < 4; mi++)
#pragma unroll
        for (int ni = 0; ni < 8; ni++) {
            const int row = m0 + wm * 64 + mi * 16 + (lane >> 2);
            const int col = n0 + wn * 64 + ni * 8 + (lane & 3) * 2;
            float* p = g_xg + (size_t)row * N_DIM + col;
            float2 v0, v1;
            v0.x = acc[mi][ni][0]; v0.y = acc[mi][ni][1];
            v1.x = acc[mi][ni][2]; v1.y = acc[mi][ni][3];
            *(float2*)p = v0;
            *(float2*)(p + 8 * N_DIM) = v1;
        }
#undef LDG_A
#undef STS_A
#undef CPA_B
}

// ===========================================================================
// Kernel L: LSTM recurrence (unchanged from R2, 289us)
// ===========================================================================
__device__ __forceinline__ float fsig(float x) { return 1.f / (1.f + __expf(-x)); }
__device__ __forceinline__ float ftanh(float x) { return 1.f - 2.f / (__expf(2.f * x) + 1.f); }

#define US_FLOATS (512 * 108)
#define SM2_FLOATS (US_FLOATS + 256 + 1024)

__global__ __launch_bounds__(512) void lstm_rec(const float* __restrict__ Uh,
                                                const float* __restrict__ bias,
                                                const float* __restrict__ Wout,
                                                const float* __restrict__ bout,
                                                float* __restrict__ out) {
    extern __shared__ float smf[];
    float* Us = smf;
    float* hs = smf + US_FLOATS;
    float* zs = hs + 256;

    const int tid = threadIdx.x;
    const int g   = tid;
    const int b0  = blockIdx.x * 2;

    for (int k = 0; k < 104; k++) Us[g * 108 + k] = Uh[k * 512 + g];
    float wreg[24];
#pragma unroll
    for (int r = 0; r < 24; r++) wreg[r] = Uh[(104 + r) * 512 + g];
    const float bg  = bias[g];
    const int gate  = g >> 7;

    if (tid < 256) hs[tid] = 0.f;
    float c = 0.f;
    __syncthreads();

    const float* xp0 = g_xg + ((size_t)b0 * 128) * 512 + g;
    const float* xp1 = g_xg + ((size_t)(b0 + 1) * 128) * 512 + g;
    float x0 = xp0[0];
    float x1 = xp1[0];

    for (int t = 0; t < 128; t++) {
        float z0 = x0 + bg;
        float z1 = x1 + bg;
        if (t + 1 < 128) {
            x0 = xp0[(t + 1) * 512];
            x1 = xp1[(t + 1) * 512];
        }
        const float4* uv = (const float4*)(Us + g * 108);
        const float4* h0 = (const float4*)hs;
        const float4* h1 = (const float4*)(hs + 128);
#pragma unroll
        for (int q = 0; q < 26; q++) {
            float4 u = uv[q];
            float4 ha = h0[q];
            float4 hb = h1[q];
            z0 += u.x * ha.x; z0 += u.y * ha.y; z0 += u.z * ha.z; z0 += u.w * ha.w;
            z1 += u.x * hb.x; z1 += u.y * hb.y; z1 += u.z * hb.z; z1 += u.w * hb.w;
        }
#pragma unroll
        for (int r = 0; r < 24; r++) {
            z0 += wreg[r] * hs[104 + r];
            z1 += wreg[r] * hs[128 + 104 + r];
        }
        float a0, a1;
        if (gate == 2) { a0 = ftanh(z0); a1 = ftanh(z1); }
        else           { a0 = fsig(z0);  a1 = fsig(z1);  }
        zs[g]       = a0;
        zs[512 + g] = a1;
        __syncthreads();
        if (tid < 256) {
            const int bl = tid >> 7;
            const int jj = tid & 127;
            const float* zb = zs + bl * 512;
            const float ig = zb[jj];
            const float fg = zb[128 + jj];
            const float gg = zb[256 + jj];
            const float og = zb[384 + jj];
            c = fg * c + ig * gg;
            hs[bl * 128 + jj] = og * ftanh(c);
        }
        __syncthreads();
    }

    if (tid < 256) {
        const int bl = tid >> 7;
        const int jj = tid & 127;
        const float h = hs[bl * 128 + jj];
        float p0 = h * Wout[jj * 2 + 0];
        float p1 = h * Wout[jj * 2 + 1];
#pragma unroll
        for (int off = 16; off > 0; off >>= 1) {
            p0 += __shfl_down_sync(0xffffffffu, p0, off);
            p1 += __shfl_down_sync(0xffffffffu, p1, off);
        }
        if ((tid & 31) == 0) {
            const int w = tid >> 5;
            zs[w * 2 + 0] = p0;
            zs[w * 2 + 1] = p1;
        }
    }
    __syncthreads();
    if (tid < 2) {
        float s0 = bout[0], s1 = bout[1];
#pragma unroll
        for (int w = 0; w < 4; w++) {
            s0 += zs[(tid * 4 + w) * 2 + 0];
            s1 += zs[(tid * 4 + w) * 2 + 1];
        }
        out[(b0 + tid) * 2 + 0] = s0;
        out[(b0 + tid) * 2 + 1] = s1;
    }
}

// ===========================================================================
extern "C" void kernel_launch(void* const* d_in, const int* in_sizes, int n_in,
                              void* d_out, int out_size) {
    const float* x    = (const float*)d_in[0];
    const float* Wi   = (const float*)d_in[1];
    const float* Uh   = (const float*)d_in[2];
    const float* b    = (const float*)d_in[3];
    const float* Wout = (const float*)d_in[4];
    const float* bout = (const float*)d_in[5];
    float* out = (float*)d_out;

    dim3 gp(K_DIM / 32, N_DIM / 32);
    prep_w<<<gp, dim3(32, 32)>>>(Wi);

    cudaFuncSetAttribute(gemm_hmma, cudaFuncAttributeMaxDynamicSharedMemorySize,
                         GEMM_SMEM);
    dim3 gg(N_DIM / 256, M_DIM / 128);          // (2, 256)
    gemm_hmma<<<gg, 256, GEMM_SMEM>>>(x);

    const size_t smem2 = SM2_FLOATS * sizeof(float);
    cudaFuncSetAttribute(lstm_rec, cudaFuncAttributeMaxDynamicSharedMemorySize,
                         (int)smem2);
    lstm_rec<<<128, 512, smem2>>>(Uh, b, Wout, bout, out);
}